// round 2
// baseline (speedup 1.0000x reference)
#include <cuda_runtime.h>

#define NU 200000
#define NR 200000
#define HDIM 64
#define EDGES 4000000
#define SCAN_B 1024
#define M2 (2 * NU)

typedef unsigned long long ull;

// ---------------- static device scratch ----------------
__device__ float g_xr0[(size_t)NR * HDIM];
__device__ float g_xr1[(size_t)NR * HDIM];
__device__ float g_xu1[(size_t)NU * HDIM];
__device__ float g_xu2[(size_t)NU * HDIM];
__device__ float g_mean_r[(size_t)NR * HDIM];
__device__ float g_mean_u[(size_t)NU * HDIM];
__device__ float g_mean_r2[(size_t)NR * HDIM];
__device__ float g_mean_u2[(size_t)NU * HDIM];
__device__ int   g_nbr_r[EDGES];
__device__ int   g_nbr_u[EDGES];
__device__ int   g_off_u[NU + 1];
__device__ int   g_off_r[NR + 1];
__device__ int   g_deg[M2];
__device__ int   g_cur[M2];
__device__ int   g_bsum[SCAN_B];

// ---------------- CSR build ----------------
__global__ void k_zero(int* deg, int* cur, int n) {
    int i = blockIdx.x * blockDim.x + threadIdx.x;
    if (i < n) { deg[i] = 0; cur[i] = 0; }
}

__global__ void k_count(const int* __restrict__ ei, int* __restrict__ deg, int e) {
    int i = blockIdx.x * blockDim.x + threadIdx.x;
    if (i < e) {
        atomicAdd(&deg[ei[i]], 1);           // user src
        atomicAdd(&deg[NU + ei[e + i]], 1);  // recipe dst
    }
}

__global__ void k_scan1(const int* __restrict__ deg, int* __restrict__ bsum, int n) {
    __shared__ int sh[SCAN_B];
    int i = blockIdx.x * SCAN_B + threadIdx.x;
    sh[threadIdx.x] = (i < n) ? deg[i] : 0;
    __syncthreads();
    for (int s = SCAN_B / 2; s > 0; s >>= 1) {
        if (threadIdx.x < s) sh[threadIdx.x] += sh[threadIdx.x + s];
        __syncthreads();
    }
    if (threadIdx.x == 0) bsum[blockIdx.x] = sh[0];
}

__global__ void k_scan2(int* bsum, int nb) {
    __shared__ int sh[SCAN_B];
    int v = (threadIdx.x < nb) ? bsum[threadIdx.x] : 0;
    sh[threadIdx.x] = v;
    __syncthreads();
    for (int s = 1; s < SCAN_B; s <<= 1) {
        int t = (threadIdx.x >= s) ? sh[threadIdx.x - s] : 0;
        __syncthreads();
        sh[threadIdx.x] += t;
        __syncthreads();
    }
    if (threadIdx.x < nb) bsum[threadIdx.x] = sh[threadIdx.x] - v;  // exclusive
}

__global__ void k_scan3(const int* __restrict__ deg, const int* __restrict__ bsum,
                        int* __restrict__ off_u, int* __restrict__ off_r, int n, int etot) {
    __shared__ int sh[SCAN_B];
    int i = blockIdx.x * SCAN_B + threadIdx.x;
    int v = (i < n) ? deg[i] : 0;
    sh[threadIdx.x] = v;
    __syncthreads();
    for (int s = 1; s < SCAN_B; s <<= 1) {
        int t = (threadIdx.x >= s) ? sh[threadIdx.x - s] : 0;
        __syncthreads();
        sh[threadIdx.x] += t;
        __syncthreads();
    }
    int excl = sh[threadIdx.x] - v + bsum[blockIdx.x];
    if (i < n) {
        if (i < NU) off_u[i] = excl;
        else        off_r[i - NU] = excl - etot;
        if (i == NU) off_u[NU] = excl;           // == etot
        if (i == n - 1) off_r[NR] = excl + v - etot;
    }
}

__global__ void k_fill(const int* __restrict__ ei,
                       const int* __restrict__ off_u, const int* __restrict__ off_r,
                       int* __restrict__ cur,
                       int* __restrict__ nbr_u, int* __restrict__ nbr_r, int e) {
    int i = blockIdx.x * blockDim.x + threadIdx.x;
    if (i < e) {
        int s = ei[i], d = ei[e + i];
        int pu = atomicAdd(&cur[s], 1);
        nbr_u[off_u[s] + pu] = d;
        int pr = atomicAdd(&cur[NU + d], 1);
        nbr_r[off_r[d] + pr] = s;
    }
}

// ---------------- mean aggregation: warp per dst node ----------------
__device__ __forceinline__ void agg_one(int w, const int* __restrict__ off,
                                        const int* __restrict__ nbr,
                                        const float* __restrict__ xsrc,
                                        float* __restrict__ dst) {
    int lane = threadIdx.x & 31;
    int beg = off[w], end = off[w + 1];
    const float2* X = (const float2*)xsrc;
    float vx = 0.f, vy = 0.f;
    for (int j = beg; j < end; j += 32) {
        int cnt = end - j; if (cnt > 32) cnt = 32;
        int idx = (lane < cnt) ? nbr[j + lane] : 0;
        int t = 0;
        for (; t + 8 <= cnt; t += 8) {  // deep MLP: 8 gathers in flight
            int r0 = __shfl_sync(0xffffffffu, idx, t);
            int r1 = __shfl_sync(0xffffffffu, idx, t + 1);
            int r2 = __shfl_sync(0xffffffffu, idx, t + 2);
            int r3 = __shfl_sync(0xffffffffu, idx, t + 3);
            int r4 = __shfl_sync(0xffffffffu, idx, t + 4);
            int r5 = __shfl_sync(0xffffffffu, idx, t + 5);
            int r6 = __shfl_sync(0xffffffffu, idx, t + 6);
            int r7 = __shfl_sync(0xffffffffu, idx, t + 7);
            float2 v0 = X[r0 * 32 + lane];
            float2 v1 = X[r1 * 32 + lane];
            float2 v2 = X[r2 * 32 + lane];
            float2 v3 = X[r3 * 32 + lane];
            float2 v4 = X[r4 * 32 + lane];
            float2 v5 = X[r5 * 32 + lane];
            float2 v6 = X[r6 * 32 + lane];
            float2 v7 = X[r7 * 32 + lane];
            vx += ((v0.x + v1.x) + (v2.x + v3.x)) + ((v4.x + v5.x) + (v6.x + v7.x));
            vy += ((v0.y + v1.y) + (v2.y + v3.y)) + ((v4.y + v5.y) + (v6.y + v7.y));
        }
        for (; t < cnt; t++) {
            int r = __shfl_sync(0xffffffffu, idx, t);
            float2 v = X[r * 32 + lane];
            vx += v.x; vy += v.y;
        }
    }
    float inv = 1.0f / fmaxf((float)(end - beg), 1.0f);
    ((float2*)dst)[w * 32 + lane] = make_float2(vx * inv, vy * inv);
}

// ---------------- transform: out = A0@W0 + bias + A1@W1 (+relu), FFMA2 path ----------------
// 256 rows x 64 cols per block, 256 threads, per-thread 8 rows x 8 cols (4 col-pairs).
#define FMA2(d, a, b) asm("fma.rn.f32x2 %0, %1, %2, %0;" : "+l"(d) : "l"(a), "l"(b))

__device__ __forceinline__ void transform_block(
    int tb, const float* __restrict__ A0, const float* __restrict__ A1,
    const float* __restrict__ W0, const float* __restrict__ W1,
    const float* __restrict__ bias, float* __restrict__ out,
    int n, int relu, float* smem) {
    float* sA = smem;              // 256 x 65 (padded)
    float* sW = smem + 256 * 65;   // 64 x 64
    const int t  = threadIdx.x;
    const int tx = t & 7;          // col group: cols 8*tx .. 8*tx+7
    const int ty = t >> 3;         // row group: rows 8*ty .. 8*ty+7 (0..31)
    const int rbase = tb * 256;

    ull acc[8][4];
#pragma unroll
    for (int i = 0; i < 8; i++)
#pragma unroll
        for (int j = 0; j < 4; j++) acc[i][j] = 0ull;

#pragma unroll
    for (int ph = 0; ph < 2; ph++) {
        const float* A = ph ? A1 : A0;
        const float* W = ph ? W1 : W0;
        __syncthreads();
#pragma unroll
        for (int u = 0; u < 4; u++)
            ((float4*)sW)[t + u * 256] = ((const float4*)W)[t + u * 256];
#pragma unroll
        for (int u = 0; u < 16; u++) {
            int idx = t + u * 256;
            int r = idx >> 4, kc = idx & 15;
            int gr = rbase + r; if (gr >= n) gr = rbase;  // clamp (discarded on store)
            float4 v = ((const float4*)(A + (size_t)gr * 64))[kc];
            float* dp = sA + r * 65 + kc * 4;
            dp[0] = v.x; dp[1] = v.y; dp[2] = v.z; dp[3] = v.w;
        }
        __syncthreads();

        const ull* sW2 = (const ull*)sW;
#pragma unroll 4
        for (int k = 0; k < 64; k++) {
            ull w2[4];
#pragma unroll
            for (int j = 0; j < 4; j++) w2[j] = sW2[k * 32 + tx * 4 + j];
            ull a2[8];
#pragma unroll
            for (int i = 0; i < 8; i++) {
                unsigned av = __float_as_uint(sA[(ty * 8 + i) * 65 + k]);
                asm("mov.b64 %0, {%1, %1};" : "=l"(a2[i]) : "r"(av));
            }
#pragma unroll
            for (int i = 0; i < 8; i++)
#pragma unroll
                for (int j = 0; j < 4; j++)
                    FMA2(acc[i][j], a2[i], w2[j]);
        }
    }

    float4 b0 = ((const float4*)bias)[tx * 2];
    float4 b1 = ((const float4*)bias)[tx * 2 + 1];
    float bc[8] = {b0.x, b0.y, b0.z, b0.w, b1.x, b1.y, b1.z, b1.w};
#pragma unroll
    for (int i = 0; i < 8; i++) {
        int row = rbase + ty * 8 + i;
        if (row >= n) continue;
        float c[8];
#pragma unroll
        for (int j = 0; j < 4; j++) {
            unsigned lo, hi;
            asm("mov.b64 {%0, %1}, %2;" : "=r"(lo), "=r"(hi) : "l"(acc[i][j]));
            c[2 * j]     = __uint_as_float(lo) + bc[2 * j];
            c[2 * j + 1] = __uint_as_float(hi) + bc[2 * j + 1];
        }
        if (relu) {
#pragma unroll
            for (int j = 0; j < 8; j++) c[j] = fmaxf(c[j], 0.f);
        }
        float4* op = (float4*)(out + (size_t)row * 64 + tx * 8);
        op[0] = make_float4(c[0], c[1], c[2], c[3]);
        op[1] = make_float4(c[4], c[5], c[6], c[7]);
    }
}

// ---------------- fused: transform blocks interleaved with aggregation blocks ----------------
__global__ void __launch_bounds__(256) k_fused_ta(
    const float* __restrict__ A0, const float* __restrict__ A1,
    const float* __restrict__ W0, const float* __restrict__ W1,
    const float* __restrict__ bias, float* __restrict__ trout, int trn, int relu,
    int trblocks, int mod,
    const int* __restrict__ off, const int* __restrict__ nbr,
    const float* __restrict__ asrc, float* __restrict__ adst, int an) {
    extern __shared__ float smem[];
    int bid = blockIdx.x;
    if (mod == 1 || bid % mod == 0) {
        int tb = (mod == 1) ? bid : bid / mod;
        if (tb < trblocks)
            transform_block(tb, A0, A1, W0, W1, bias, trout, trn, relu, smem);
        return;
    }
    int ab = bid - bid / mod - 1;
    int w = ab * 8 + (threadIdx.x >> 5);
    if (w < an) agg_one(w, off, nbr, asrc, adst);
}

// ---------------- fused: x_recipe init interleaved with aggregation ----------------
__global__ void __launch_bounds__(256) k_fused_ia(
    const float* __restrict__ rx, const float* __restrict__ lw,
    const float* __restrict__ lb, const float* __restrict__ remb,
    float* __restrict__ xout,
    const int* __restrict__ off, const int* __restrict__ nbr,
    const float* __restrict__ asrc, float* __restrict__ adst, int an) {
    __shared__ float slw[640];
    __shared__ float slb[64];
    int bid = blockIdx.x;
    if (bid % 5 == 0) {
        int ib = bid / 5;
        int t = threadIdx.x;
        for (int i = t; i < 640; i += 256) slw[i] = lw[i];
        if (t < 64) slb[t] = lb[t];
        __syncthreads();
#pragma unroll
        for (int u = 0; u < 2; u++) {
            int idx4 = ib * 512 + u * 256 + t;   // float4 index, < NR*16
            int r = idx4 >> 4;
            int h0 = (idx4 & 15) * 4;
            float4 acc = make_float4(slb[h0], slb[h0 + 1], slb[h0 + 2], slb[h0 + 3]);
            const float* xr = rx + r * 10;
#pragma unroll
            for (int k = 0; k < 10; k++) {
                float xv = xr[k];
                const float* wr = slw + k * 64 + h0;
                acc.x = fmaf(xv, wr[0], acc.x);
                acc.y = fmaf(xv, wr[1], acc.y);
                acc.z = fmaf(xv, wr[2], acc.z);
                acc.w = fmaf(xv, wr[3], acc.w);
            }
            float4 e = ((const float4*)remb)[idx4];
            acc.x += e.x; acc.y += e.y; acc.z += e.z; acc.w += e.w;
            ((float4*)xout)[idx4] = acc;
        }
        return;
    }
    int ab = bid - bid / 5 - 1;
    int w = ab * 8 + (threadIdx.x >> 5);
    if (w < an) agg_one(w, off, nbr, asrc, adst);
}

// ---------------- classifier: warp per label edge ----------------
__global__ void k_classify(const int* __restrict__ eli, const float* __restrict__ xu,
                           const float* __restrict__ xr, float* __restrict__ out, int nl) {
    int w = (blockIdx.x * blockDim.x + threadIdx.x) >> 5;
    int lane = threadIdx.x & 31;
    if (w >= nl) return;
    int a = eli[w], b = eli[nl + w];
    float2 va = ((const float2*)xu)[a * 32 + lane];
    float2 vb = ((const float2*)xr)[b * 32 + lane];
    float s = va.x * vb.x + va.y * vb.y;
#pragma unroll
    for (int o = 16; o > 0; o >>= 1) s += __shfl_down_sync(0xffffffffu, s, o);
    if (lane == 0) out[w] = s;
}

// ---------------- launch ----------------
extern "C" void kernel_launch(void* const* d_in, const int* in_sizes, int n_in,
                              void* d_out, int out_size) {
    const float* recipe_x   = (const float*)d_in[2];
    const int*   edge_index = (const int*)d_in[3];
    const int*   eli        = (const int*)d_in[4];
    const float* user_emb   = (const float*)d_in[5];
    const float* recipe_emb = (const float*)d_in[6];
    const float* lin_w      = (const float*)d_in[7];
    const float* lin_b      = (const float*)d_in[8];
    const float* Wl         = (const float*)d_in[9];
    const float* bl         = (const float*)d_in[10];
    const float* Wr         = (const float*)d_in[11];
    float* out = (float*)d_out;
    int E_ = in_sizes[3] / 2;
    int L_ = in_sizes[4] / 2;

    float *xr0, *xr1, *xu1, *xu2, *mean_r, *mean_u, *mean_r2, *mean_u2;
    int *nbr_r, *nbr_u, *off_u, *off_r, *deg, *cur, *bsum;
    cudaGetSymbolAddress((void**)&xr0,     g_xr0);
    cudaGetSymbolAddress((void**)&xr1,     g_xr1);
    cudaGetSymbolAddress((void**)&xu1,     g_xu1);
    cudaGetSymbolAddress((void**)&xu2,     g_xu2);
    cudaGetSymbolAddress((void**)&mean_r,  g_mean_r);
    cudaGetSymbolAddress((void**)&mean_u,  g_mean_u);
    cudaGetSymbolAddress((void**)&mean_r2, g_mean_r2);
    cudaGetSymbolAddress((void**)&mean_u2, g_mean_u2);
    cudaGetSymbolAddress((void**)&nbr_r,   g_nbr_r);
    cudaGetSymbolAddress((void**)&nbr_u,   g_nbr_u);
    cudaGetSymbolAddress((void**)&off_u,   g_off_u);
    cudaGetSymbolAddress((void**)&off_r,   g_off_r);
    cudaGetSymbolAddress((void**)&deg,     g_deg);
    cudaGetSymbolAddress((void**)&cur,     g_cur);
    cudaGetSymbolAddress((void**)&bsum,    g_bsum);

    const int TR_SMEM = (256 * 65 + 64 * 64) * 4;  // 82944 bytes
    cudaFuncSetAttribute(k_fused_ta, cudaFuncAttributeMaxDynamicSharedMemorySize, TR_SMEM);

    int nb2 = (M2 + SCAN_B - 1) / SCAN_B;  // 391

    // CSR build
    k_zero <<<(M2 + 255) / 256, 256>>>(deg, cur, M2);
    k_count<<<(E_ + 255) / 256, 256>>>(edge_index, deg, E_);
    k_scan1<<<nb2, SCAN_B>>>(deg, bsum, M2);
    k_scan2<<<1, SCAN_B>>>(bsum, nb2);
    k_scan3<<<nb2, SCAN_B>>>(deg, bsum, off_u, off_r, M2, E_);
    k_fill <<<(E_ + 255) / 256, 256>>>(edge_index, off_u, off_r, cur, nbr_u, nbr_r, E_);

    // K1: init x_recipe (xr0) || agg_r0 (user_emb -> mean_r)
    k_fused_ia<<<31250, 256>>>(recipe_x, lin_w, lin_b, recipe_emb, xr0,
                               off_r, nbr_r, user_emb, mean_r, NR);

    const int TRB = (NR + 255) / 256;  // 782
    const int MOD = 33;
    const int GRID_TA = TRB * MOD;     // 25806

    // K2: tr_r0 (mean_r, xr0 -> xr1, relu) || agg_u0 (xr0 -> mean_u)
    k_fused_ta<<<GRID_TA, 256, TR_SMEM>>>(mean_r, xr0, Wl, Wr, bl, xr1, NR, 1,
                                          TRB, MOD, off_u, nbr_u, xr0, mean_u, NU);
    // K3: tr_u0 (mean_u, user_emb -> xu1, relu) || agg_u1 (xr1 -> mean_u2)
    k_fused_ta<<<GRID_TA, 256, TR_SMEM>>>(mean_u, user_emb, Wl + 4096, Wr + 4096, bl + 64,
                                          xu1, NU, 1,
                                          TRB, MOD, off_u, nbr_u, xr1, mean_u2, NU);
    // K4: tr_u1 (mean_u2, xu1 -> xu2) || agg_r1 (xu1 -> mean_r2)
    k_fused_ta<<<GRID_TA, 256, TR_SMEM>>>(mean_u2, xu1, Wl + 12288, Wr + 12288, bl + 192,
                                          xu2, NU, 0,
                                          TRB, MOD, off_r, nbr_r, xu1, mean_r2, NR);
    // K5: tr_r1 (mean_r2, xr1 -> xr0 final)
    k_fused_ta<<<TRB, 256, TR_SMEM>>>(mean_r2, xr1, Wl + 8192, Wr + 8192, bl + 128,
                                      xr0, NR, 0,
                                      TRB, 1, (const int*)0, (const int*)0,
                                      (const float*)0, (float*)0, 0);

    // classifier
    k_classify<<<(L_ * 32 + 255) / 256, 256>>>(eli, xu2, xr0, out, L_);
}

// round 3
// speedup vs baseline: 2.2141x; 2.2141x over previous
#include <cuda_runtime.h>

#define NU 200000
#define NR 200000
#define HDIM 64
#define EDGES 4000000
#define SCAN_B 1024
#define M2 (2 * NU)

typedef unsigned long long ull;

// ---------------- static device scratch ----------------
__device__ float g_xr0[(size_t)NR * HDIM];
__device__ float g_xr1[(size_t)NR * HDIM];
__device__ float g_xu1[(size_t)NU * HDIM];
__device__ float g_xu2[(size_t)NU * HDIM];
__device__ float g_mean_r[(size_t)NR * HDIM];
__device__ float g_mean_u[(size_t)NU * HDIM];
__device__ float g_mean_r2[(size_t)NR * HDIM];
__device__ float g_mean_u2[(size_t)NU * HDIM];
__device__ int   g_nbr_r[EDGES];
__device__ int   g_nbr_u[EDGES];
__device__ int   g_off_u[NU + 1];
__device__ int   g_off_r[NR + 1];
__device__ int   g_deg[M2];
__device__ int   g_cur[M2];
__device__ int   g_bsum[SCAN_B];

// ---------------- CSR build ----------------
__global__ void k_zero(int* deg, int* cur, int n) {
    int i = blockIdx.x * blockDim.x + threadIdx.x;
    if (i < n) { deg[i] = 0; cur[i] = 0; }
}

__global__ void k_count(const int* __restrict__ ei, int* __restrict__ deg, int e) {
    int i = blockIdx.x * blockDim.x + threadIdx.x;
    if (i < e) {
        atomicAdd(&deg[ei[i]], 1);           // user src
        atomicAdd(&deg[NU + ei[e + i]], 1);  // recipe dst
    }
}

__global__ void k_scan1(const int* __restrict__ deg, int* __restrict__ bsum, int n) {
    __shared__ int sh[SCAN_B];
    int i = blockIdx.x * SCAN_B + threadIdx.x;
    sh[threadIdx.x] = (i < n) ? deg[i] : 0;
    __syncthreads();
    for (int s = SCAN_B / 2; s > 0; s >>= 1) {
        if (threadIdx.x < s) sh[threadIdx.x] += sh[threadIdx.x + s];
        __syncthreads();
    }
    if (threadIdx.x == 0) bsum[blockIdx.x] = sh[0];
}

__global__ void k_scan2(int* bsum, int nb) {
    __shared__ int sh[SCAN_B];
    int v = (threadIdx.x < nb) ? bsum[threadIdx.x] : 0;
    sh[threadIdx.x] = v;
    __syncthreads();
    for (int s = 1; s < SCAN_B; s <<= 1) {
        int t = (threadIdx.x >= s) ? sh[threadIdx.x - s] : 0;
        __syncthreads();
        sh[threadIdx.x] += t;
        __syncthreads();
    }
    if (threadIdx.x < nb) bsum[threadIdx.x] = sh[threadIdx.x] - v;  // exclusive
}

__global__ void k_scan3(const int* __restrict__ deg, const int* __restrict__ bsum,
                        int* __restrict__ off_u, int* __restrict__ off_r, int n, int etot) {
    __shared__ int sh[SCAN_B];
    int i = blockIdx.x * SCAN_B + threadIdx.x;
    int v = (i < n) ? deg[i] : 0;
    sh[threadIdx.x] = v;
    __syncthreads();
    for (int s = 1; s < SCAN_B; s <<= 1) {
        int t = (threadIdx.x >= s) ? sh[threadIdx.x - s] : 0;
        __syncthreads();
        sh[threadIdx.x] += t;
        __syncthreads();
    }
    int excl = sh[threadIdx.x] - v + bsum[blockIdx.x];
    if (i < n) {
        if (i < NU) off_u[i] = excl;
        else        off_r[i - NU] = excl - etot;
        if (i == NU) off_u[NU] = excl;
        if (i == n - 1) off_r[NR] = excl + v - etot;
    }
}

__global__ void k_fill(const int* __restrict__ ei,
                       const int* __restrict__ off_u, const int* __restrict__ off_r,
                       int* __restrict__ cur,
                       int* __restrict__ nbr_u, int* __restrict__ nbr_r, int e) {
    int i = blockIdx.x * blockDim.x + threadIdx.x;
    if (i < e) {
        int s = ei[i], d = ei[e + i];
        int pu = atomicAdd(&cur[s], 1);
        nbr_u[off_u[s] + pu] = d;
        int pr = atomicAdd(&cur[NU + d], 1);
        nbr_r[off_r[d] + pr] = s;
    }
}

// ---------------- mean aggregation: warp per dst node, deep MLP ----------------
__global__ void __launch_bounds__(256) k_aggregate(
    const int* __restrict__ off, const int* __restrict__ nbr,
    const float* __restrict__ xsrc, float* __restrict__ mean, int n) {
    int w = (blockIdx.x * blockDim.x + threadIdx.x) >> 5;
    int lane = threadIdx.x & 31;
    if (w >= n) return;
    int beg = off[w], end = off[w + 1];
    const float2* X = (const float2*)xsrc;
    float vx = 0.f, vy = 0.f;
    for (int j = beg; j < end; j += 32) {
        int cnt = end - j; if (cnt > 32) cnt = 32;
        int idx = (lane < cnt) ? nbr[j + lane] : 0;
        int t = 0;
        for (; t + 8 <= cnt; t += 8) {
            int r0 = __shfl_sync(0xffffffffu, idx, t);
            int r1 = __shfl_sync(0xffffffffu, idx, t + 1);
            int r2 = __shfl_sync(0xffffffffu, idx, t + 2);
            int r3 = __shfl_sync(0xffffffffu, idx, t + 3);
            int r4 = __shfl_sync(0xffffffffu, idx, t + 4);
            int r5 = __shfl_sync(0xffffffffu, idx, t + 5);
            int r6 = __shfl_sync(0xffffffffu, idx, t + 6);
            int r7 = __shfl_sync(0xffffffffu, idx, t + 7);
            float2 v0 = X[r0 * 32 + lane];
            float2 v1 = X[r1 * 32 + lane];
            float2 v2 = X[r2 * 32 + lane];
            float2 v3 = X[r3 * 32 + lane];
            float2 v4 = X[r4 * 32 + lane];
            float2 v5 = X[r5 * 32 + lane];
            float2 v6 = X[r6 * 32 + lane];
            float2 v7 = X[r7 * 32 + lane];
            vx += ((v0.x + v1.x) + (v2.x + v3.x)) + ((v4.x + v5.x) + (v6.x + v7.x));
            vy += ((v0.y + v1.y) + (v2.y + v3.y)) + ((v4.y + v5.y) + (v6.y + v7.y));
        }
        for (; t < cnt; t++) {
            int r = __shfl_sync(0xffffffffu, idx, t);
            float2 v = X[r * 32 + lane];
            vx += v.x; vy += v.y;
        }
    }
    float inv = 1.0f / fmaxf((float)(end - beg), 1.0f);
    ((float2*)mean)[w * 32 + lane] = make_float2(vx * inv, vy * inv);
}

// ---------------- transform: out = A0@W0 + bias + A1@W1 (+relu), FFMA2 ----------------
// 128 rows x 64 cols per block, 256 threads, per-thread 4 rows x 8 cols.
// smem 49664 B -> 4 blocks/SM.
#define FMA2(d, a, b) asm("fma.rn.f32x2 %0, %1, %2, %0;" : "+l"(d) : "l"(a), "l"(b))

__global__ void __launch_bounds__(256) k_transform(
    const float* __restrict__ A0, const float* __restrict__ A1,
    const float* __restrict__ W0, const float* __restrict__ W1,
    const float* __restrict__ bias, float* __restrict__ out, int n, int relu) {
    extern __shared__ float smem[];
    float* sA = smem;              // 128 x 65 (padded)
    float* sW = smem + 128 * 65;   // 64 x 64
    const int t  = threadIdx.x;
    const int tx = t & 7;          // col group: cols 8*tx .. 8*tx+7
    const int ty = t >> 3;         // row group: rows 4*ty .. 4*ty+3 (0..31)
    const int rbase = blockIdx.x * 128;

    ull acc[4][4];
#pragma unroll
    for (int i = 0; i < 4; i++)
#pragma unroll
        for (int j = 0; j < 4; j++) acc[i][j] = 0ull;

#pragma unroll
    for (int ph = 0; ph < 2; ph++) {
        const float* A = ph ? A1 : A0;
        const float* W = ph ? W1 : W0;
        __syncthreads();
#pragma unroll
        for (int u = 0; u < 4; u++)
            ((float4*)sW)[t + u * 256] = ((const float4*)W)[t + u * 256];
#pragma unroll
        for (int u = 0; u < 8; u++) {
            int idx4 = t + u * 256;            // float4 id within 128x64 tile
            int r = idx4 >> 4, kc = idx4 & 15;
            int gr = rbase + r; if (gr >= n) gr = rbase;  // clamp (discarded on store)
            float4 v = ((const float4*)(A + (size_t)gr * 64))[kc];
            float* dp = sA + r * 65 + kc * 4;
            dp[0] = v.x; dp[1] = v.y; dp[2] = v.z; dp[3] = v.w;
        }
        __syncthreads();

        const ull* sW2 = (const ull*)sW;
#pragma unroll 8
        for (int k = 0; k < 64; k++) {
            ull w2[4];
#pragma unroll
            for (int j = 0; j < 4; j++) w2[j] = sW2[k * 32 + tx * 4 + j];
            ull a2[4];
#pragma unroll
            for (int i = 0; i < 4; i++) {
                unsigned av = __float_as_uint(sA[(ty * 4 + i) * 65 + k]);
                asm("mov.b64 %0, {%1, %1};" : "=l"(a2[i]) : "r"(av));
            }
#pragma unroll
            for (int i = 0; i < 4; i++)
#pragma unroll
                for (int j = 0; j < 4; j++)
                    FMA2(acc[i][j], a2[i], w2[j]);
        }
    }

    float4 b0 = ((const float4*)bias)[tx * 2];
    float4 b1 = ((const float4*)bias)[tx * 2 + 1];
    float bc[8] = {b0.x, b0.y, b0.z, b0.w, b1.x, b1.y, b1.z, b1.w};
#pragma unroll
    for (int i = 0; i < 4; i++) {
        int row = rbase + ty * 4 + i;
        if (row >= n) continue;
        float c[8];
#pragma unroll
        for (int j = 0; j < 4; j++) {
            unsigned lo, hi;
            asm("mov.b64 {%0, %1}, %2;" : "=r"(lo), "=r"(hi) : "l"(acc[i][j]));
            c[2 * j]     = __uint_as_float(lo) + bc[2 * j];
            c[2 * j + 1] = __uint_as_float(hi) + bc[2 * j + 1];
        }
        if (relu) {
#pragma unroll
            for (int j = 0; j < 8; j++) c[j] = fmaxf(c[j], 0.f);
        }
        float4* op = (float4*)(out + (size_t)row * 64 + tx * 8);
        op[0] = make_float4(c[0], c[1], c[2], c[3]);
        op[1] = make_float4(c[4], c[5], c[6], c[7]);
    }
}

// ---------------- x_recipe init ----------------
__global__ void __launch_bounds__(256) k_init_recipe(
    const float* __restrict__ rx, const float* __restrict__ lw,
    const float* __restrict__ lb, const float* __restrict__ remb,
    float* __restrict__ xout, int n) {
    __shared__ float slw[640];
    __shared__ float slb[64];
    int t = threadIdx.x;
    for (int i = t; i < 640; i += 256) slw[i] = lw[i];
    if (t < 64) slb[t] = lb[t];
    __syncthreads();
    int idx4 = blockIdx.x * 256 + t;     // float4 index
    if (idx4 >= n * 16) return;
    int r = idx4 >> 4;
    int h0 = (idx4 & 15) * 4;
    float4 acc = make_float4(slb[h0], slb[h0 + 1], slb[h0 + 2], slb[h0 + 3]);
    const float* xr = rx + r * 10;
#pragma unroll
    for (int k = 0; k < 10; k++) {
        float xv = xr[k];
        const float* wr = slw + k * 64 + h0;
        acc.x = fmaf(xv, wr[0], acc.x);
        acc.y = fmaf(xv, wr[1], acc.y);
        acc.z = fmaf(xv, wr[2], acc.z);
        acc.w = fmaf(xv, wr[3], acc.w);
    }
    float4 e = ((const float4*)remb)[idx4];
    acc.x += e.x; acc.y += e.y; acc.z += e.z; acc.w += e.w;
    ((float4*)xout)[idx4] = acc;
}

// ---------------- classifier: warp per label edge ----------------
__global__ void k_classify(const int* __restrict__ eli, const float* __restrict__ xu,
                           const float* __restrict__ xr, float* __restrict__ out, int nl) {
    int w = (blockIdx.x * blockDim.x + threadIdx.x) >> 5;
    int lane = threadIdx.x & 31;
    if (w >= nl) return;
    int a = eli[w], b = eli[nl + w];
    float2 va = ((const float2*)xu)[a * 32 + lane];
    float2 vb = ((const float2*)xr)[b * 32 + lane];
    float s = va.x * vb.x + va.y * vb.y;
#pragma unroll
    for (int o = 16; o > 0; o >>= 1) s += __shfl_down_sync(0xffffffffu, s, o);
    if (lane == 0) out[w] = s;
}

// ---------------- launch: fork-join capture with 2 streams ----------------
extern "C" void kernel_launch(void* const* d_in, const int* in_sizes, int n_in,
                              void* d_out, int out_size) {
    const float* recipe_x   = (const float*)d_in[2];
    const int*   edge_index = (const int*)d_in[3];
    const int*   eli        = (const int*)d_in[4];
    const float* user_emb   = (const float*)d_in[5];
    const float* recipe_emb = (const float*)d_in[6];
    const float* lin_w      = (const float*)d_in[7];
    const float* lin_b      = (const float*)d_in[8];
    const float* Wl         = (const float*)d_in[9];
    const float* bl         = (const float*)d_in[10];
    const float* Wr         = (const float*)d_in[11];
    float* out = (float*)d_out;
    int E_ = in_sizes[3] / 2;
    int L_ = in_sizes[4] / 2;

    float *xr0, *xr1, *xu1, *xu2, *mean_r, *mean_u, *mean_r2, *mean_u2;
    int *nbr_r, *nbr_u, *off_u, *off_r, *deg, *cur, *bsum;
    cudaGetSymbolAddress((void**)&xr0,     g_xr0);
    cudaGetSymbolAddress((void**)&xr1,     g_xr1);
    cudaGetSymbolAddress((void**)&xu1,     g_xu1);
    cudaGetSymbolAddress((void**)&xu2,     g_xu2);
    cudaGetSymbolAddress((void**)&mean_r,  g_mean_r);
    cudaGetSymbolAddress((void**)&mean_u,  g_mean_u);
    cudaGetSymbolAddress((void**)&mean_r2, g_mean_r2);
    cudaGetSymbolAddress((void**)&mean_u2, g_mean_u2);
    cudaGetSymbolAddress((void**)&nbr_r,   g_nbr_r);
    cudaGetSymbolAddress((void**)&nbr_u,   g_nbr_u);
    cudaGetSymbolAddress((void**)&off_u,   g_off_u);
    cudaGetSymbolAddress((void**)&off_r,   g_off_r);
    cudaGetSymbolAddress((void**)&deg,     g_deg);
    cudaGetSymbolAddress((void**)&cur,     g_cur);
    cudaGetSymbolAddress((void**)&bsum,    g_bsum);

    const int TR_SMEM = (128 * 65 + 64 * 64) * 4;  // 49664 B
    cudaFuncSetAttribute(k_transform, cudaFuncAttributeMaxDynamicSharedMemorySize, TR_SMEM);

    const int TRB  = (NU + 127) / 128;               // 1563 (NU == NR)
    const int AGGB = (NR * 32 + 255) / 256;          // warp per node, 8 warps/block
    int nb2 = (M2 + SCAN_B - 1) / SCAN_B;

    cudaStream_t s2;
    cudaStreamCreate(&s2);
    cudaEvent_t evStart, evInit, evAggR0, evAggU0, evTrR0, evTrU0, evAggU1, evAggR1, evJoin;
    cudaEventCreateWithFlags(&evStart, cudaEventDisableTiming);
    cudaEventCreateWithFlags(&evInit,  cudaEventDisableTiming);
    cudaEventCreateWithFlags(&evAggR0, cudaEventDisableTiming);
    cudaEventCreateWithFlags(&evAggU0, cudaEventDisableTiming);
    cudaEventCreateWithFlags(&evTrR0,  cudaEventDisableTiming);
    cudaEventCreateWithFlags(&evTrU0,  cudaEventDisableTiming);
    cudaEventCreateWithFlags(&evAggU1, cudaEventDisableTiming);
    cudaEventCreateWithFlags(&evAggR1, cudaEventDisableTiming);
    cudaEventCreateWithFlags(&evJoin,  cudaEventDisableTiming);

    // fork
    cudaEventRecord(evStart, 0);
    cudaStreamWaitEvent(s2, evStart, 0);

    // B: x_recipe init (independent of CSR)
    k_init_recipe<<<(NR * 16 + 255) / 256, 256, 0, s2>>>(recipe_x, lin_w, lin_b,
                                                         recipe_emb, xr0, NR);
    cudaEventRecord(evInit, s2);

    // A: CSR build
    k_zero <<<(M2 + 255) / 256, 256>>>(deg, cur, M2);
    k_count<<<(E_ + 255) / 256, 256>>>(edge_index, deg, E_);
    k_scan1<<<nb2, SCAN_B>>>(deg, bsum, M2);
    k_scan2<<<1, SCAN_B>>>(bsum, nb2);
    k_scan3<<<nb2, SCAN_B>>>(deg, bsum, off_u, off_r, M2, E_);
    k_fill <<<(E_ + 255) / 256, 256>>>(edge_index, off_u, off_r, cur, nbr_u, nbr_r, E_);

    // A: agg_r0 (user_emb -> mean_r)
    k_aggregate<<<AGGB, 256>>>(off_r, nbr_r, user_emb, mean_r, NR);
    cudaEventRecord(evAggR0, 0);

    // A: agg_u0 (xr0 -> mean_u), needs init
    cudaStreamWaitEvent(0, evInit, 0);
    k_aggregate<<<AGGB, 256>>>(off_u, nbr_u, xr0, mean_u, NU);
    cudaEventRecord(evAggU0, 0);

    // B: tr_r0 (mean_r, xr0 -> xr1, relu)  [overlaps agg_u0]
    cudaStreamWaitEvent(s2, evAggR0, 0);
    k_transform<<<TRB, 256, TR_SMEM, s2>>>(mean_r, xr0, Wl, Wr, bl, xr1, NR, 1);
    cudaEventRecord(evTrR0, s2);

    // B: tr_u0 (mean_u, user_emb -> xu1, relu)  [overlaps agg_u1]
    cudaStreamWaitEvent(s2, evAggU0, 0);
    k_transform<<<TRB, 256, TR_SMEM, s2>>>(mean_u, user_emb, Wl + 4096, Wr + 4096,
                                           bl + 64, xu1, NU, 1);
    cudaEventRecord(evTrU0, s2);

    // A: agg_u1 (xr1 -> mean_u2)
    cudaStreamWaitEvent(0, evTrR0, 0);
    k_aggregate<<<AGGB, 256>>>(off_u, nbr_u, xr1, mean_u2, NU);
    cudaEventRecord(evAggU1, 0);

    // A: agg_r1 (xu1 -> mean_r2)
    cudaStreamWaitEvent(0, evTrU0, 0);
    k_aggregate<<<AGGB, 256>>>(off_r, nbr_r, xu1, mean_r2, NR);
    cudaEventRecord(evAggR1, 0);

    // B: tr_u1 (mean_u2, xu1 -> xu2)  [overlaps agg_r1]
    cudaStreamWaitEvent(s2, evAggU1, 0);
    k_transform<<<TRB, 256, TR_SMEM, s2>>>(mean_u2, xu1, Wl + 12288, Wr + 12288,
                                           bl + 192, xu2, NU, 0);

    // B: tr_r1 (mean_r2, xr1 -> xr0 final)
    cudaStreamWaitEvent(s2, evAggR1, 0);
    k_transform<<<TRB, 256, TR_SMEM, s2>>>(mean_r2, xr1, Wl + 8192, Wr + 8192,
                                           bl + 128, xr0, NR, 0);

    // B: classifier
    k_classify<<<(L_ * 32 + 255) / 256, 256, 0, s2>>>(eli, xu2, xr0, out, L_);

    // join
    cudaEventRecord(evJoin, s2);
    cudaStreamWaitEvent(0, evJoin, 0);

    cudaEventDestroy(evStart); cudaEventDestroy(evInit);
    cudaEventDestroy(evAggR0); cudaEventDestroy(evAggU0);
    cudaEventDestroy(evTrR0);  cudaEventDestroy(evTrU0);
    cudaEventDestroy(evAggU1); cudaEventDestroy(evAggR1);
    cudaEventDestroy(evJoin);
    cudaStreamDestroy(s2);
}